// round 2
// baseline (speedup 1.0000x reference)
#include <cuda_runtime.h>
#include <cuda_bf16.h>
#include <mma.h>

using namespace nvcuda;

// Problem constants
#define L_DIM 1024
#define B_DIM 32
#define IN_DIM 1024
#define D_DIM 1024
#define M_DIM (L_DIM * B_DIM)      // 32768
#define N_DIM (4 * D_DIM)          // 4096
#define K_DIM IN_DIM               // 1024

// Scratch for U = x @ W  : 32768 x 4096 fp32 = 512 MB (device global, no alloc)
__device__ float g_U[(size_t)M_DIM * N_DIM];

// ---------------------------------------------------------------------------
// GEMM: C[M,N] = A[M,K] @ B[K,N], fp32 in/out, tf32 tensor cores (wmma legacy
// path). Block tile 128x128, K-step 16, 8 warps (2x4), warp tile 64x32.
// ---------------------------------------------------------------------------
__global__ __launch_bounds__(256) void gemm_tf32_kernel(
    const float* __restrict__ A,
    const float* __restrict__ Bm,
    float* __restrict__ C)
{
    __shared__ __align__(16) float As[128][16];       // 8 KB
    __shared__ __align__(16) float Bs[16][136];       // 8.7 KB (pad to kill conflicts)

    const int tid = threadIdx.x;
    const int row0 = blockIdx.y * 128;
    const int col0 = blockIdx.x * 128;
    const int warpId = tid >> 5;
    const int wr = warpId >> 2;    // 0..1 -> 64-row slab
    const int wc = warpId & 3;     // 0..3 -> 32-col slab

    wmma::fragment<wmma::accumulator, 16, 16, 8, float> acc[4][2];
#pragma unroll
    for (int mi = 0; mi < 4; mi++)
#pragma unroll
        for (int ni = 0; ni < 2; ni++)
            wmma::fill_fragment(acc[mi][ni], 0.0f);

    for (int k0 = 0; k0 < K_DIM; k0 += 16) {
        // Load A tile 128x16 (row-major, ld=K_DIM): 512 float4, 2 per thread
#pragma unroll
        for (int it = 0; it < 2; it++) {
            int idx = tid + it * 256;
            int r = idx >> 2;
            int c = (idx & 3) * 4;
            float4 v = *(const float4*)&A[(size_t)(row0 + r) * K_DIM + k0 + c];
            *(float4*)&As[r][c] = v;
        }
        // Load B tile 16x128 (row-major, ld=N_DIM): 512 float4, 2 per thread
#pragma unroll
        for (int it = 0; it < 2; it++) {
            int idx = tid + it * 256;
            int r = idx >> 5;
            int c = (idx & 31) * 4;
            float4 v = *(const float4*)&Bm[(size_t)(k0 + r) * N_DIM + col0 + c];
            *(float4*)&Bs[r][c] = v;
        }
        __syncthreads();

#pragma unroll
        for (int ks = 0; ks < 16; ks += 8) {
            wmma::fragment<wmma::matrix_a, 16, 16, 8, wmma::precision::tf32,
                           wmma::row_major> af[4];
            wmma::fragment<wmma::matrix_b, 16, 16, 8, wmma::precision::tf32,
                           wmma::row_major> bf[2];
#pragma unroll
            for (int mi = 0; mi < 4; mi++) {
                wmma::load_matrix_sync(af[mi], &As[wr * 64 + mi * 16][ks], 16);
#pragma unroll
                for (int e = 0; e < af[mi].num_elements; e++)
                    af[mi].x[e] = wmma::__float_to_tf32(af[mi].x[e]);
            }
#pragma unroll
            for (int ni = 0; ni < 2; ni++) {
                wmma::load_matrix_sync(bf[ni], &Bs[ks][wc * 32 + ni * 16], 136);
#pragma unroll
                for (int e = 0; e < bf[ni].num_elements; e++)
                    bf[ni].x[e] = wmma::__float_to_tf32(bf[ni].x[e]);
            }
#pragma unroll
            for (int mi = 0; mi < 4; mi++)
#pragma unroll
                for (int ni = 0; ni < 2; ni++)
                    wmma::mma_sync(acc[mi][ni], af[mi], bf[ni], acc[mi][ni]);
        }
        __syncthreads();
    }

#pragma unroll
    for (int mi = 0; mi < 4; mi++)
#pragma unroll
        for (int ni = 0; ni < 2; ni++) {
            size_t r = (size_t)(row0 + wr * 64 + mi * 16);
            size_t c = (size_t)(col0 + wc * 32 + ni * 16);
            wmma::store_matrix_sync(&C[r * N_DIM + c], acc[mi][ni], N_DIM,
                                    wmma::mem_row_major);
        }
}

// ---------------------------------------------------------------------------
// SRU scan: one thread per (b,d) lane, sequential over L with 4-deep prefetch
// of U (float4 per step). U float4 index for (l,b,d) = l*32768 + b*1024 + d.
// ---------------------------------------------------------------------------
__device__ __forceinline__ float sigmoidf_fast(float z) {
    return 1.0f / (1.0f + __expf(-z));
}

__global__ __launch_bounds__(256) void sru_scan_kernel(
    const float* __restrict__ U,
    const float* __restrict__ c0,
    const float* __restrict__ V,
    const float* __restrict__ bias,
    float* __restrict__ h_out,
    float* __restrict__ c_out)
{
    const int t = blockIdx.x * blockDim.x + threadIdx.x;   // 0..32767
    const int d = t & (D_DIM - 1);

    const float vf = V[d];
    const float vr = V[D_DIM + d];
    const float bf = bias[d];
    const float br = bias[D_DIM + d];
    float c = c0[t];

    const float4* __restrict__ Up = (const float4*)U + t;  // stride 32768 per l
    float* __restrict__ hp = h_out + t;                    // stride 32768 per l

    float4 buf[4];
#pragma unroll
    for (int j = 0; j < 4; j++) buf[j] = Up[(size_t)j * (M_DIM / L_DIM * D_DIM)];

    for (int l = 0; l < L_DIM; l += 4) {
        float4 cur[4];
#pragma unroll
        for (int j = 0; j < 4; j++) cur[j] = buf[j];
        if (l + 4 < L_DIM) {
#pragma unroll
            for (int j = 0; j < 4; j++)
                buf[j] = Up[(size_t)(l + 4 + j) * (B_DIM * D_DIM)];
        }
#pragma unroll
        for (int j = 0; j < 4; j++) {
            float4 u = cur[j];
            float f = sigmoidf_fast(u.y + c * vf + bf);
            float r = sigmoidf_fast(u.z + c * vr + br);
            c = u.x + (c - u.x) * f;
            float h = (tanhf(c) - u.w) * r + u.w;
            hp[(size_t)(l + j) * (B_DIM * D_DIM)] = h;
        }
    }

    if (c_out) c_out[t] = c;   // c_last laid out (B, D) -> index t
}

// ---------------------------------------------------------------------------
// Launch
// ---------------------------------------------------------------------------
extern "C" void kernel_launch(void* const* d_in, const int* in_sizes, int n_in,
                              void* d_out, int out_size)
{
    const float* x    = (const float*)d_in[0];   // (L,B,IN)
    const float* c0   = (const float*)d_in[1];   // (B,D)
    const float* W    = (const float*)d_in[2];   // (IN,4D)
    const float* V    = (const float*)d_in[3];   // (2D)
    const float* bias = (const float*)d_in[4];   // (2D)
    float* out = (float*)d_out;

    float* U = nullptr;
    cudaGetSymbolAddress((void**)&U, g_U);

    dim3 grid(N_DIM / 128, M_DIM / 128);
    gemm_tf32_kernel<<<grid, 256>>>(x, W, U);

    const size_t LBD = (size_t)L_DIM * B_DIM * D_DIM;
    float* c_out = ((size_t)out_size > LBD) ? (out + LBD) : nullptr;

    sru_scan_kernel<<<(B_DIM * D_DIM) / 256, 256>>>(U, c0, V, bias, out, c_out);
}

// round 4
// speedup vs baseline: 2.6413x; 2.6413x over previous
#include <cuda_runtime.h>
#include <cuda_bf16.h>
#include <cstdint>

// ---------------------------------------------------------------------------
// Problem constants
// ---------------------------------------------------------------------------
#define L_DIM 1024
#define B_DIM 32
#define IN_DIM 1024
#define D_DIM 1024
#define M_DIM (L_DIM * B_DIM)      // 32768
#define N_DIM (4 * D_DIM)          // 4096
#define K_DIM IN_DIM               // 1024

// GEMM tiling
#define BM 128
#define BN 256
#define BKB 32                     // K per stage
#define NKB (K_DIM / BKB)          // 32 stages of K
#define ASTG_F (BM * BKB)          // 4096 floats / stage (16 KB)
#define BSTG_F (BN * BKB)          // 8192 floats / stage (32 KB)
#define STG_F (ASTG_F + BSTG_F)    // 12288 floats (48 KB)
#define NPIPE 4
#define GEMM_SMEM (NPIPE * STG_F * 4)   // 196608 B

// Scratch (device globals; no allocation allowed)
__device__ float g_U[(size_t)M_DIM * N_DIM];            // 512 MB
__device__ float g_Ap[(size_t)M_DIM * K_DIM];           // 128 MB  fragment-ordered x
__device__ float g_Bp[(size_t)N_DIM * K_DIM];           // 16 MB   fragment-ordered W

// ---------------------------------------------------------------------------
// helpers
// ---------------------------------------------------------------------------
__device__ __forceinline__ uint32_t smem_u32(const void* p) {
    uint32_t a;
    asm("{ .reg .u64 t; cvta.to.shared.u64 t, %1; cvt.u32.u64 %0, t; }"
        : "=r"(a) : "l"(p));
    return a;
}
__device__ __forceinline__ void cp16(uint32_t s, const void* g) {
    asm volatile("cp.async.cg.shared.global [%0], [%1], 16;" :: "r"(s), "l"(g));
}
__device__ __forceinline__ float tf32r(float f) {
    uint32_t u;
    asm("cvt.rna.tf32.f32 %0, %1;" : "=r"(u) : "f"(f));
    return __uint_as_float(u);
}

#define LDS128(r0, r1, r2, r3, addr)                                           \
    asm volatile("ld.shared.v4.b32 {%0,%1,%2,%3}, [%4];"                       \
                 : "=r"(r0), "=r"(r1), "=r"(r2), "=r"(r3) : "r"(addr))

#define MMA_TF32(d, a, b0, b1)                                                 \
    asm volatile(                                                              \
        "mma.sync.aligned.m16n8k8.row.col.f32.tf32.tf32.f32 "                  \
        "{%0,%1,%2,%3}, {%4,%5,%6,%7}, {%8,%9}, {%0,%1,%2,%3};"                \
        : "+f"((d)[0]), "+f"((d)[1]), "+f"((d)[2]), "+f"((d)[3])               \
        : "r"((a)[0]), "r"((a)[1]), "r"((a)[2]), "r"((a)[3]),                  \
          "r"(b0), "r"(b1))

// ---------------------------------------------------------------------------
// Prep A: x (L,B,IN fp32) -> g_Ap, tf32-rounded, MMA-fragment order.
// Tile T = ((m_blk*NKB + k_blk)*8 + mt)*4 + kt  (m16 x k8 tile)
// Thread t of the tile's warp stores float4 {a0,a1,a2,a3}:
//   a0=(r,c) a1=(r+8,c) a2=(r,c+4) a3=(r+8,c+4), r=t/4, c=t%4  (PTX tf32 A map)
// ---------------------------------------------------------------------------
__global__ __launch_bounds__(256) void prep_x_kernel(
    const float* __restrict__ x, float* __restrict__ Ap)
{
    int T = blockIdx.x * 8 + (threadIdx.x >> 5);
    int t = threadIdx.x & 31;
    int kt    = T & 3;
    int mt    = (T >> 2) & 7;
    int k_blk = (T >> 5) & (NKB - 1);
    int m_blk = T >> 10;
    int r = m_blk * BM + mt * 16 + (t >> 2);
    int c = k_blk * BKB + kt * 8 + (t & 3);
    const float* xr = x + (size_t)r * K_DIM + c;
    float4 v;
    v.x = tf32r(xr[0]);
    v.y = tf32r(xr[(size_t)8 * K_DIM]);
    v.z = tf32r(xr[4]);
    v.w = tf32r(xr[(size_t)8 * K_DIM + 4]);
    ((float4*)Ap)[(size_t)T * 32 + t] = v;
}

// ---------------------------------------------------------------------------
// Prep B: W (IN,4D fp32, row-major [k][n]) -> g_Bp, tf32, fragment order.
// Tile Tb = ((n_blk*NKB + k_blk)*16 + np)*4 + kt   (k8 x n16 pair tile)
// Thread t stores float4 {b0,b1,b0',b1'}: b0=(k=t%4, n=t/4), b1=(k+4, n),
// primes = same with n+8.  (PTX tf32 B col-major map)
// ---------------------------------------------------------------------------
__global__ __launch_bounds__(256) void prep_W_kernel(
    const float* __restrict__ W, float* __restrict__ Bp)
{
    int T = blockIdx.x * 8 + (threadIdx.x >> 5);
    int t = threadIdx.x & 31;
    int kt    = T & 3;
    int np    = (T >> 2) & 15;
    int k_blk = (T >> 6) & (NKB - 1);
    int n_blk = T >> 11;
    int k = k_blk * BKB + kt * 8 + (t & 3);
    int n = n_blk * BN + np * 16 + (t >> 2);
    const float* wp = W + (size_t)k * N_DIM + n;
    float4 v;
    v.x = tf32r(wp[0]);
    v.y = tf32r(wp[(size_t)4 * N_DIM]);
    v.z = tf32r(wp[8]);
    v.w = tf32r(wp[(size_t)4 * N_DIM + 8]);
    ((float4*)Bp)[(size_t)T * 32 + t] = v;
}

// ---------------------------------------------------------------------------
// GEMM: C[M][N] += Ap . Bp^T via mma.sync m16n8k8 tf32.
// CTA 128x256, 8 warps (2x4), warp tile 64x64, 4-stage cp.async pipeline.
// ---------------------------------------------------------------------------
__global__ __launch_bounds__(256, 1) void gemm_tf32_mma_kernel(
    const float* __restrict__ Ap,
    const float* __restrict__ Bp,
    float* __restrict__ C)
{
    extern __shared__ __align__(16) float smem[];
    const uint32_t sbase = smem_u32(smem);
    const int tid  = threadIdx.x;
    const int wid  = tid >> 5;
    const int lane = tid & 31;
    const int wr   = wid >> 2;     // 0..1: 64-row slab
    const int wc   = wid & 3;      // 0..3: 64-col slab
    const int mb   = blockIdx.y;
    const int nb   = blockIdx.x;

    const float* gA = Ap + (size_t)mb * NKB * ASTG_F;
    const float* gB = Bp + (size_t)nb * NKB * BSTG_F;

    auto load_stage = [&](int s) {
        uint32_t sa = sbase + (uint32_t)(s & (NPIPE - 1)) * (STG_F * 4);
        const char* ga = (const char*)(gA + (size_t)s * ASTG_F);
        const char* gb = (const char*)(gB + (size_t)s * BSTG_F);
#pragma unroll
        for (int i = 0; i < 4; i++)
            cp16(sa + tid * 16 + i * 4096, ga + tid * 16 + i * 4096);
        uint32_t sb = sa + 16384;
#pragma unroll
        for (int i = 0; i < 8; i++)
            cp16(sb + tid * 16 + i * 4096, gb + tid * 16 + i * 4096);
        asm volatile("cp.async.commit_group;" ::: "memory");
    };

    load_stage(0);
    load_stage(1);
    load_stage(2);

    float acc[4][8][4] = {};

    for (int kb = 0; kb < NKB; kb++) {
        if (kb <= NKB - 3)      asm volatile("cp.async.wait_group 2;" ::: "memory");
        else if (kb == NKB - 2) asm volatile("cp.async.wait_group 1;" ::: "memory");
        else                    asm volatile("cp.async.wait_group 0;" ::: "memory");
        __syncthreads();

        if (kb + 3 < NKB) load_stage(kb + 3);

        uint32_t sa = sbase + (uint32_t)(kb & (NPIPE - 1)) * (STG_F * 4);
        uint32_t sb = sa + 16384;

#pragma unroll
        for (int kt = 0; kt < 4; kt++) {
            uint32_t a[4][4];
#pragma unroll
            for (int mi = 0; mi < 4; mi++) {
                int mt = wr * 4 + mi;
                uint32_t addr = sa + (uint32_t)(((mt * 4 + kt) * 32 + lane) * 16);
                LDS128(a[mi][0], a[mi][1], a[mi][2], a[mi][3], addr);
            }
            uint32_t b[4][4];
#pragma unroll
            for (int pi = 0; pi < 4; pi++) {
                int np = wc * 4 + pi;
                uint32_t addr = sb + (uint32_t)(((np * 4 + kt) * 32 + lane) * 16);
                LDS128(b[pi][0], b[pi][1], b[pi][2], b[pi][3], addr);
            }
#pragma unroll
            for (int mi = 0; mi < 4; mi++)
#pragma unroll
                for (int pi = 0; pi < 4; pi++) {
                    MMA_TF32(acc[mi][pi * 2],     a[mi], b[pi][0], b[pi][1]);
                    MMA_TF32(acc[mi][pi * 2 + 1], a[mi], b[pi][2], b[pi][3]);
                }
        }
    }

    // Epilogue: c0,c1 at (row=lane/4, col=(lane%4)*2), c2,c3 at row+8.
    float* Cb = C + (size_t)(mb * BM + wr * 64 + (lane >> 2)) * N_DIM
                  + nb * BN + wc * 64 + (lane & 3) * 2;
#pragma unroll
    for (int mi = 0; mi < 4; mi++) {
#pragma unroll
        for (int ni = 0; ni < 8; ni++) {
            float* p = Cb + (size_t)mi * 16 * N_DIM + ni * 8;
            *(float2*)p = make_float2(acc[mi][ni][0], acc[mi][ni][1]);
            *(float2*)(p + (size_t)8 * N_DIM) =
                make_float2(acc[mi][ni][2], acc[mi][ni][3]);
        }
    }
}

// ---------------------------------------------------------------------------
// SRU scan: one thread per (b,d) lane, 4-deep float4 prefetch along L.
// ---------------------------------------------------------------------------
__device__ __forceinline__ float sigmoidf_fast(float z) {
    return 1.0f / (1.0f + __expf(-z));
}

__global__ __launch_bounds__(256) void sru_scan_kernel(
    const float* __restrict__ U,
    const float* __restrict__ c0,
    const float* __restrict__ V,
    const float* __restrict__ bias,
    float* __restrict__ h_out,
    float* __restrict__ c_out)
{
    const int t = blockIdx.x * blockDim.x + threadIdx.x;   // 0..32767
    const int d = t & (D_DIM - 1);

    const float vf = V[d];
    const float vr = V[D_DIM + d];
    const float bf = bias[d];
    const float br = bias[D_DIM + d];
    float c = c0[t];

    const float4* __restrict__ Up = (const float4*)U + t;  // stride 32768 per l
    float* __restrict__ hp = h_out + t;

    float4 buf[4];
#pragma unroll
    for (int j = 0; j < 4; j++) buf[j] = Up[(size_t)j * (B_DIM * D_DIM)];

    for (int l = 0; l < L_DIM; l += 4) {
        float4 cur[4];
#pragma unroll
        for (int j = 0; j < 4; j++) cur[j] = buf[j];
        if (l + 4 < L_DIM) {
#pragma unroll
            for (int j = 0; j < 4; j++)
                buf[j] = Up[(size_t)(l + 4 + j) * (B_DIM * D_DIM)];
        }
#pragma unroll
        for (int j = 0; j < 4; j++) {
            float4 u = cur[j];
            float f = sigmoidf_fast(u.y + c * vf + bf);
            float r = sigmoidf_fast(u.z + c * vr + br);
            c = u.x + (c - u.x) * f;
            float h = (tanhf(c) - u.w) * r + u.w;
            hp[(size_t)(l + j) * (B_DIM * D_DIM)] = h;
        }
    }

    if (c_out) c_out[t] = c;
}

// ---------------------------------------------------------------------------
// Launch
// ---------------------------------------------------------------------------
extern "C" void kernel_launch(void* const* d_in, const int* in_sizes, int n_in,
                              void* d_out, int out_size)
{
    const float* x    = (const float*)d_in[0];   // (L,B,IN)
    const float* c0   = (const float*)d_in[1];   // (B,D)
    const float* W    = (const float*)d_in[2];   // (IN,4D)
    const float* V    = (const float*)d_in[3];   // (2D)
    const float* bias = (const float*)d_in[4];   // (2D)
    float* out = (float*)d_out;

    float *U = nullptr, *Ap = nullptr, *Bp = nullptr;
    cudaGetSymbolAddress((void**)&U, g_U);
    cudaGetSymbolAddress((void**)&Ap, g_Ap);
    cudaGetSymbolAddress((void**)&Bp, g_Bp);

    cudaFuncSetAttribute(gemm_tf32_mma_kernel,
                         cudaFuncAttributeMaxDynamicSharedMemorySize, GEMM_SMEM);

    // prep: 262144 A tiles / 8 per block ; 32768 B tiles / 8 per block
    prep_x_kernel<<<32768, 256>>>(x, Ap);
    prep_W_kernel<<<4096, 256>>>(W, Bp);

    // GEMM: grid.x = N tiles (fast-varying -> A reuse within a wave via L2)
    gemm_tf32_mma_kernel<<<dim3(N_DIM / BN, M_DIM / BM), 256, GEMM_SMEM>>>(
        Ap, Bp, U);

    const size_t LBD = (size_t)L_DIM * B_DIM * D_DIM;
    float* c_out = ((size_t)out_size > LBD) ? (out + LBD) : nullptr;
    sru_scan_kernel<<<(B_DIM * D_DIM) / 256, 256>>>(U, c0, V, bias, out, c_out);
}

// round 6
// speedup vs baseline: 4.3797x; 1.6581x over previous
#include <cuda_runtime.h>
#include <cuda_fp16.h>
#include <cstdint>

// ---------------------------------------------------------------------------
// Problem constants
// ---------------------------------------------------------------------------
#define L_DIM 1024
#define B_DIM 32
#define IN_DIM 1024
#define D_DIM 1024
#define M_DIM (L_DIM * B_DIM)      // 32768
#define N_DIM (4 * D_DIM)          // 4096
#define K_DIM IN_DIM               // 1024

// GEMM tiling (fp16 operands)
#define BM 128
#define BN 256
#define BKB 32                     // K per stage
#define NKB (K_DIM / BKB)          // 32 stages
#define ASTG_B (BM * BKB * 2)      // 8192 B / stage
#define BSTG_B (BN * BKB * 2)      // 16384 B / stage
#define STG_B (ASTG_B + BSTG_B)    // 24576 B
#define NPIPE 4
#define GEMM_SMEM (NPIPE * STG_B)  // 98304 B

// Scratch (device globals; no allocation allowed)
__device__ float  g_U[(size_t)M_DIM * N_DIM];           // 512 MB
__device__ __half g_Ap[(size_t)M_DIM * K_DIM];          // 64 MB  fragment-ordered x
__device__ __half g_Bp[(size_t)N_DIM * K_DIM];          // 8 MB   fragment-ordered W

// ---------------------------------------------------------------------------
// helpers
// ---------------------------------------------------------------------------
__device__ __forceinline__ uint32_t smem_u32(const void* p) {
    uint32_t a;
    asm("{ .reg .u64 t; cvta.to.shared.u64 t, %1; cvt.u32.u64 %0, t; }"
        : "=r"(a) : "l"(p));
    return a;
}
__device__ __forceinline__ void cp16(uint32_t s, const void* g) {
    asm volatile("cp.async.cg.shared.global [%0], [%1], 16;" :: "r"(s), "l"(g));
}
__device__ __forceinline__ uint32_t h2_u32(__half2 h) {
    uint32_t u;
    memcpy(&u, &h, 4);
    return u;
}

#define LDS128(r0, r1, r2, r3, addr)                                           \
    asm volatile("ld.shared.v4.b32 {%0,%1,%2,%3}, [%4];"                       \
                 : "=r"(r0), "=r"(r1), "=r"(r2), "=r"(r3) : "r"(addr))

#define MMA_F16(d, a, b0, b1)                                                  \
    asm volatile(                                                              \
        "mma.sync.aligned.m16n8k16.row.col.f32.f16.f16.f32 "                   \
        "{%0,%1,%2,%3}, {%4,%5,%6,%7}, {%8,%9}, {%0,%1,%2,%3};"                \
        : "+f"((d)[0]), "+f"((d)[1]), "+f"((d)[2]), "+f"((d)[3])               \
        : "r"((a)[0]), "r"((a)[1]), "r"((a)[2]), "r"((a)[3]),                  \
          "r"(b0), "r"(b1))

// ---------------------------------------------------------------------------
// Prep A: x (fp32) -> g_Ap, fp16, m16n8k16 A-fragment order.
// Tile T = ((m_blk*NKB + k_blk)*8 + mt)*2 + kt   (m16 x k16 tile)
// Thread t of the tile's warp stores uint4 {a0,a1,a2,a3}; r=t/4, c=(t%4)*2:
//   a0={A[r][c],A[r][c+1]} a1={A[r+8][c],..} a2={A[r][c+8],..} a3={A[r+8][c+8],..}
// ---------------------------------------------------------------------------
__global__ __launch_bounds__(256) void prep_x_kernel(
    const float* __restrict__ x, __half* __restrict__ Ap)
{
    int T = blockIdx.x * 8 + (threadIdx.x >> 5);
    int t = threadIdx.x & 31;
    int kt    = T & 1;
    int mt    = (T >> 1) & 7;
    int k_blk = (T >> 4) & (NKB - 1);
    int m_blk = T >> 9;
    int r = m_blk * BM + mt * 16 + (t >> 2);
    int c = k_blk * BKB + kt * 16 + (t & 3) * 2;
    const float* xr = x + (size_t)r * K_DIM + c;
    float2 v0 = *(const float2*)xr;
    float2 v1 = *(const float2*)(xr + (size_t)8 * K_DIM);
    float2 v2 = *(const float2*)(xr + 8);
    float2 v3 = *(const float2*)(xr + (size_t)8 * K_DIM + 8);
    uint4 o;
    o.x = h2_u32(__floats2half2_rn(v0.x, v0.y));
    o.y = h2_u32(__floats2half2_rn(v1.x, v1.y));
    o.z = h2_u32(__floats2half2_rn(v2.x, v2.y));
    o.w = h2_u32(__floats2half2_rn(v3.x, v3.y));
    ((uint4*)Ap)[(size_t)T * 32 + t] = o;
}

// ---------------------------------------------------------------------------
// Prep B: W [K][N] fp32 -> g_Bp, fp16, m16n8k16 B-fragment order (col-major).
// Tile T = ((n_blk*NKB + k_blk)*16 + np)*2 + kt  (k16 x n16 pair)
// Thread t stores uint4 {b0,b1,b0',b1'}; k=(t%4)*2, n=t/4:
//   b0={B[k][n],B[k+1][n]} b1={B[k+8][n],B[k+9][n]}, primes at n+8.
// ---------------------------------------------------------------------------
__global__ __launch_bounds__(256) void prep_W_kernel(
    const float* __restrict__ W, __half* __restrict__ Bp)
{
    int T = blockIdx.x * 8 + (threadIdx.x >> 5);
    int t = threadIdx.x & 31;
    int kt    = T & 1;
    int np    = (T >> 1) & 15;
    int k_blk = (T >> 5) & (NKB - 1);
    int n_blk = T >> 10;
    int k = k_blk * BKB + kt * 16 + (t & 3) * 2;
    int n = n_blk * BN + np * 16 + (t >> 2);
    const float* wp = W + (size_t)k * N_DIM + n;
    float w0  = wp[0];
    float w1  = wp[N_DIM];
    float w8  = wp[(size_t)8 * N_DIM];
    float w9  = wp[(size_t)9 * N_DIM];
    float w0b = wp[8];
    float w1b = wp[N_DIM + 8];
    float w8b = wp[(size_t)8 * N_DIM + 8];
    float w9b = wp[(size_t)9 * N_DIM + 8];
    uint4 o;
    o.x = h2_u32(__floats2half2_rn(w0, w1));
    o.y = h2_u32(__floats2half2_rn(w8, w9));
    o.z = h2_u32(__floats2half2_rn(w0b, w1b));
    o.w = h2_u32(__floats2half2_rn(w8b, w9b));
    ((uint4*)Bp)[(size_t)T * 32 + t] = o;
}

// ---------------------------------------------------------------------------
// GEMM: C[M][N] = Ap . Bp^T via mma.sync m16n8k16 fp16 (fp32 accum).
// CTA 128x256, 8 warps (2x4), warp tile 64x64, 4-stage cp.async pipeline.
// ---------------------------------------------------------------------------
__global__ __launch_bounds__(256, 1) void gemm_f16_mma_kernel(
    const __half* __restrict__ Ap,
    const __half* __restrict__ Bp,
    float* __restrict__ C)
{
    extern __shared__ __align__(16) char smem[];
    const uint32_t sbase = smem_u32(smem);
    const int tid  = threadIdx.x;
    const int wid  = tid >> 5;
    const int lane = tid & 31;
    const int wr   = wid >> 2;     // 0..1: 64-row slab
    const int wc   = wid & 3;      // 0..3: 64-col slab
    const int mb   = blockIdx.y;
    const int nb   = blockIdx.x;

    const char* gA = (const char*)(Ap) + (size_t)mb * NKB * ASTG_B;
    const char* gB = (const char*)(Bp) + (size_t)nb * NKB * BSTG_B;

    auto load_stage = [&](int s) {
        uint32_t sa = sbase + (uint32_t)(s & (NPIPE - 1)) * STG_B;
        const char* ga = gA + (size_t)s * ASTG_B;
        const char* gb = gB + (size_t)s * BSTG_B;
#pragma unroll
        for (int i = 0; i < 2; i++)
            cp16(sa + tid * 16 + i * 4096, ga + tid * 16 + i * 4096);
        uint32_t sb = sa + ASTG_B;
#pragma unroll
        for (int i = 0; i < 4; i++)
            cp16(sb + tid * 16 + i * 4096, gb + tid * 16 + i * 4096);
        asm volatile("cp.async.commit_group;" ::: "memory");
    };

    load_stage(0);
    load_stage(1);
    load_stage(2);

    float acc[4][8][4] = {};

    for (int kb = 0; kb < NKB; kb++) {
        if (kb <= NKB - 3)      asm volatile("cp.async.wait_group 2;" ::: "memory");
        else if (kb == NKB - 2) asm volatile("cp.async.wait_group 1;" ::: "memory");
        else                    asm volatile("cp.async.wait_group 0;" ::: "memory");
        __syncthreads();

        if (kb + 3 < NKB) load_stage(kb + 3);

        uint32_t sa = sbase + (uint32_t)(kb & (NPIPE - 1)) * STG_B;
        uint32_t sb = sa + ASTG_B;

#pragma unroll
        for (int kt = 0; kt < 2; kt++) {
            uint32_t a[4][4];
#pragma unroll
            for (int mi = 0; mi < 4; mi++) {
                int mt = wr * 4 + mi;
                uint32_t addr = sa + (uint32_t)(((mt * 2 + kt) * 32 + lane) * 16);
                LDS128(a[mi][0], a[mi][1], a[mi][2], a[mi][3], addr);
            }
            uint32_t b[4][4];
#pragma unroll
            for (int pi = 0; pi < 4; pi++) {
                int np = wc * 4 + pi;
                uint32_t addr = sb + (uint32_t)(((np * 2 + kt) * 32 + lane) * 16);
                LDS128(b[pi][0], b[pi][1], b[pi][2], b[pi][3], addr);
            }
#pragma unroll
            for (int mi = 0; mi < 4; mi++)
#pragma unroll
                for (int pi = 0; pi < 4; pi++) {
                    MMA_F16(acc[mi][pi * 2],     a[mi], b[pi][0], b[pi][1]);
                    MMA_F16(acc[mi][pi * 2 + 1], a[mi], b[pi][2], b[pi][3]);
                }
        }
    }

    // Epilogue: c0,c1 at (row=lane/4, col=(lane%4)*2), c2,c3 at row+8.
    float* Cb = C + (size_t)(mb * BM + wr * 64 + (lane >> 2)) * N_DIM
                  + nb * BN + wc * 64 + (lane & 3) * 2;
#pragma unroll
    for (int mi = 0; mi < 4; mi++) {
#pragma unroll
        for (int ni = 0; ni < 8; ni++) {
            float* p = Cb + (size_t)mi * 16 * N_DIM + ni * 8;
            *(float2*)p = make_float2(acc[mi][ni][0], acc[mi][ni][1]);
            *(float2*)(p + (size_t)8 * N_DIM) =
                make_float2(acc[mi][ni][2], acc[mi][ni][3]);
        }
    }
}

// ---------------------------------------------------------------------------
// SRU scan: one thread per (b,d) lane, 8-deep float4 prefetch along L.
// ---------------------------------------------------------------------------
__device__ __forceinline__ float sigmoidf_fast(float z) {
    return 1.0f / (1.0f + __expf(-z));
}

__global__ __launch_bounds__(256) void sru_scan_kernel(
    const float* __restrict__ U,
    const float* __restrict__ c0,
    const float* __restrict__ V,
    const float* __restrict__ bias,
    float* __restrict__ h_out,
    float* __restrict__ c_out)
{
    const int t = blockIdx.x * blockDim.x + threadIdx.x;   // 0..32767
    const int d = t & (D_DIM - 1);

    const float vf = V[d];
    const float vr = V[D_DIM + d];
    const float bf = bias[d];
    const float br = bias[D_DIM + d];
    float c = c0[t];

    const float4* __restrict__ Up = (const float4*)U + t;  // stride 32768 per l
    float* __restrict__ hp = h_out + t;

    float4 buf[8];
#pragma unroll
    for (int j = 0; j < 8; j++) buf[j] = Up[(size_t)j * (B_DIM * D_DIM)];

    for (int l = 0; l < L_DIM; l += 8) {
        float4 cur[8];
#pragma unroll
        for (int j = 0; j < 8; j++) cur[j] = buf[j];
        if (l + 8 < L_DIM) {
#pragma unroll
            for (int j = 0; j < 8; j++)
                buf[j] = Up[(size_t)(l + 8 + j) * (B_DIM * D_DIM)];
        }
#pragma unroll
        for (int j = 0; j < 8; j++) {
            float4 u = cur[j];
            float f = sigmoidf_fast(u.y + c * vf + bf);
            float r = sigmoidf_fast(u.z + c * vr + br);
            c = u.x + (c - u.x) * f;
            float h = (tanhf(c) - u.w) * r + u.w;
            hp[(size_t)(l + j) * (B_DIM * D_DIM)] = h;
        }
    }

    if (c_out) c_out[t] = c;
}

// ---------------------------------------------------------------------------
// Launch
// ---------------------------------------------------------------------------
extern "C" void kernel_launch(void* const* d_in, const int* in_sizes, int n_in,
                              void* d_out, int out_size)
{
    const float* x    = (const float*)d_in[0];   // (L,B,IN)
    const float* c0   = (const float*)d_in[1];   // (B,D)
    const float* W    = (const float*)d_in[2];   // (IN,4D)
    const float* V    = (const float*)d_in[3];   // (2D)
    const float* bias = (const float*)d_in[4];   // (2D)
    float* out = (float*)d_out;

    float* U = nullptr;
    __half *Ap = nullptr, *Bp = nullptr;
    cudaGetSymbolAddress((void**)&U, g_U);
    cudaGetSymbolAddress((void**)&Ap, g_Ap);
    cudaGetSymbolAddress((void**)&Bp, g_Bp);

    cudaFuncSetAttribute(gemm_f16_mma_kernel,
                         cudaFuncAttributeMaxDynamicSharedMemorySize, GEMM_SMEM);

    // prep: 131072 A tiles / 8 per block ; 16384 B tiles / 8 per block
    prep_x_kernel<<<16384, 256>>>(x, Ap);
    prep_W_kernel<<<2048, 256>>>(W, Bp);

    // GEMM: grid.x = N tiles (fast-varying -> A reuse within a wave via L2)
    gemm_f16_mma_kernel<<<dim3(N_DIM / BN, M_DIM / BM), 256, GEMM_SMEM>>>(
        Ap, Bp, U);

    const size_t LBD = (size_t)L_DIM * B_DIM * D_DIM;
    float* c_out = ((size_t)out_size > LBD) ? (out + LBD) : nullptr;
    sru_scan_kernel<<<(B_DIM * D_DIM) / 256, 256>>>(U, c0, V, bias, out, c_out);
}

// round 7
// speedup vs baseline: 4.3894x; 1.0022x over previous
#include <cuda_runtime.h>
#include <cuda_fp16.h>
#include <cstdint>

// ---------------------------------------------------------------------------
// Problem constants
// ---------------------------------------------------------------------------
#define L_DIM 1024
#define B_DIM 32
#define IN_DIM 1024
#define D_DIM 1024
#define M_DIM (L_DIM * B_DIM)      // 32768
#define N_DIM (4 * D_DIM)          // 4096
#define K_DIM IN_DIM               // 1024

// GEMM tiling (fp16 operands)
#define BM 128
#define BN 256
#define BKB 32                     // K per stage
#define NKB (K_DIM / BKB)          // 32 stages
#define ASTG_B (BM * BKB * 2)      // 8192 B / stage
#define BSTG_B (BN * BKB * 2)      // 16384 B / stage
#define STG_B (ASTG_B + BSTG_B)    // 24576 B
#define NPIPE 4
#define GEMM_SMEM (NPIPE * STG_B)  // 98304 B

// Scratch (device globals; no allocation allowed)
// U stored fp16, layout [l/2][s=b*1024+d][8] : fp16 idx = ((l>>1)*32768+s)*8 + (l&1)*4 + g
__device__ __half g_U16[(size_t)M_DIM * N_DIM];         // 256 MB
__device__ __half g_Ap[(size_t)M_DIM * K_DIM];          // 64 MB  fragment-ordered x
__device__ __half g_Bp[(size_t)N_DIM * K_DIM];          // 8 MB   fragment-ordered W

// ---------------------------------------------------------------------------
// helpers
// ---------------------------------------------------------------------------
__device__ __forceinline__ uint32_t smem_u32(const void* p) {
    uint32_t a;
    asm("{ .reg .u64 t; cvta.to.shared.u64 t, %1; cvt.u32.u64 %0, t; }"
        : "=r"(a) : "l"(p));
    return a;
}
__device__ __forceinline__ void cp16(uint32_t s, const void* g) {
    asm volatile("cp.async.cg.shared.global [%0], [%1], 16;" :: "r"(s), "l"(g));
}
__device__ __forceinline__ uint32_t h2_u32(__half2 h) {
    uint32_t u;
    memcpy(&u, &h, 4);
    return u;
}

#define LDS128(r0, r1, r2, r3, addr)                                           \
    asm volatile("ld.shared.v4.b32 {%0,%1,%2,%3}, [%4];"                       \
                 : "=r"(r0), "=r"(r1), "=r"(r2), "=r"(r3) : "r"(addr))

#define MMA_F16(d, a, b0, b1)                                                  \
    asm volatile(                                                              \
        "mma.sync.aligned.m16n8k16.row.col.f32.f16.f16.f32 "                   \
        "{%0,%1,%2,%3}, {%4,%5,%6,%7}, {%8,%9}, {%0,%1,%2,%3};"                \
        : "+f"((d)[0]), "+f"((d)[1]), "+f"((d)[2]), "+f"((d)[3])               \
        : "r"((a)[0]), "r"((a)[1]), "r"((a)[2]), "r"((a)[3]),                  \
          "r"(b0), "r"(b1))

// ---------------------------------------------------------------------------
// Prep A: x (fp32) -> g_Ap, fp16, m16n8k16 A-fragment order.
// ---------------------------------------------------------------------------
__global__ __launch_bounds__(256) void prep_x_kernel(
    const float* __restrict__ x, __half* __restrict__ Ap)
{
    int T = blockIdx.x * 8 + (threadIdx.x >> 5);
    int t = threadIdx.x & 31;
    int kt    = T & 1;
    int mt    = (T >> 1) & 7;
    int k_blk = (T >> 4) & (NKB - 1);
    int m_blk = T >> 9;
    int r = m_blk * BM + mt * 16 + (t >> 2);
    int c = k_blk * BKB + kt * 16 + (t & 3) * 2;
    const float* xr = x + (size_t)r * K_DIM + c;
    float2 v0 = *(const float2*)xr;
    float2 v1 = *(const float2*)(xr + (size_t)8 * K_DIM);
    float2 v2 = *(const float2*)(xr + 8);
    float2 v3 = *(const float2*)(xr + (size_t)8 * K_DIM + 8);
    uint4 o;
    o.x = h2_u32(__floats2half2_rn(v0.x, v0.y));
    o.y = h2_u32(__floats2half2_rn(v1.x, v1.y));
    o.z = h2_u32(__floats2half2_rn(v2.x, v2.y));
    o.w = h2_u32(__floats2half2_rn(v3.x, v3.y));
    ((uint4*)Ap)[(size_t)T * 32 + t] = o;
}

// ---------------------------------------------------------------------------
// Prep B: W [K][N] fp32 -> g_Bp, fp16, m16n8k16 B-fragment order (col-major).
// ---------------------------------------------------------------------------
__global__ __launch_bounds__(256) void prep_W_kernel(
    const float* __restrict__ W, __half* __restrict__ Bp)
{
    int T = blockIdx.x * 8 + (threadIdx.x >> 5);
    int t = threadIdx.x & 31;
    int kt    = T & 1;
    int np    = (T >> 1) & 15;
    int k_blk = (T >> 5) & (NKB - 1);
    int n_blk = T >> 10;
    int k = k_blk * BKB + kt * 16 + (t & 3) * 2;
    int n = n_blk * BN + np * 16 + (t >> 2);
    const float* wp = W + (size_t)k * N_DIM + n;
    float w0  = wp[0];
    float w1  = wp[N_DIM];
    float w8  = wp[(size_t)8 * N_DIM];
    float w9  = wp[(size_t)9 * N_DIM];
    float w0b = wp[8];
    float w1b = wp[N_DIM + 8];
    float w8b = wp[(size_t)8 * N_DIM + 8];
    float w9b = wp[(size_t)9 * N_DIM + 8];
    uint4 o;
    o.x = h2_u32(__floats2half2_rn(w0, w1));
    o.y = h2_u32(__floats2half2_rn(w8, w9));
    o.z = h2_u32(__floats2half2_rn(w0b, w1b));
    o.w = h2_u32(__floats2half2_rn(w8b, w9b));
    ((uint4*)Bp)[(size_t)T * 32 + t] = o;
}

// ---------------------------------------------------------------------------
// GEMM: U16 = Ap . Bp^T via mma.sync m16n8k16 fp16 (fp32 accum).
// CTA 128x256, 8 warps (2x4), warp tile 64x64, 4-stage cp.async pipeline.
// Epilogue converts to fp16 and scatters into the scan-friendly U16 layout.
// ---------------------------------------------------------------------------
__global__ __launch_bounds__(256, 1) void gemm_f16_mma_kernel(
    const __half* __restrict__ Ap,
    const __half* __restrict__ Bp,
    __half* __restrict__ U16)
{
    extern __shared__ __align__(16) char smem[];
    const uint32_t sbase = smem_u32(smem);
    const int tid  = threadIdx.x;
    const int wid  = tid >> 5;
    const int lane = tid & 31;
    const int wr   = wid >> 2;     // 0..1: 64-row slab
    const int wc   = wid & 3;      // 0..3: 64-col slab
    const int mb   = blockIdx.y;
    const int nb   = blockIdx.x;

    const char* gA = (const char*)(Ap) + (size_t)mb * NKB * ASTG_B;
    const char* gB = (const char*)(Bp) + (size_t)nb * NKB * BSTG_B;

    auto load_stage = [&](int s) {
        uint32_t sa = sbase + (uint32_t)(s & (NPIPE - 1)) * STG_B;
        const char* ga = gA + (size_t)s * ASTG_B;
        const char* gb = gB + (size_t)s * BSTG_B;
#pragma unroll
        for (int i = 0; i < 2; i++)
            cp16(sa + tid * 16 + i * 4096, ga + tid * 16 + i * 4096);
        uint32_t sb = sa + ASTG_B;
#pragma unroll
        for (int i = 0; i < 4; i++)
            cp16(sb + tid * 16 + i * 4096, gb + tid * 16 + i * 4096);
        asm volatile("cp.async.commit_group;" ::: "memory");
    };

    load_stage(0);
    load_stage(1);
    load_stage(2);

    float acc[4][8][4] = {};

    for (int kb = 0; kb < NKB; kb++) {
        if (kb <= NKB - 3)      asm volatile("cp.async.wait_group 2;" ::: "memory");
        else if (kb == NKB - 2) asm volatile("cp.async.wait_group 1;" ::: "memory");
        else                    asm volatile("cp.async.wait_group 0;" ::: "memory");
        __syncthreads();

        if (kb + 3 < NKB) load_stage(kb + 3);

        uint32_t sa = sbase + (uint32_t)(kb & (NPIPE - 1)) * STG_B;
        uint32_t sb = sa + ASTG_B;

#pragma unroll
        for (int kt = 0; kt < 2; kt++) {
            uint32_t a[4][4];
#pragma unroll
            for (int mi = 0; mi < 4; mi++) {
                int mt = wr * 4 + mi;
                uint32_t addr = sa + (uint32_t)(((mt * 2 + kt) * 32 + lane) * 16);
                LDS128(a[mi][0], a[mi][1], a[mi][2], a[mi][3], addr);
            }
            uint32_t b[4][4];
#pragma unroll
            for (int pi = 0; pi < 4; pi++) {
                int np = wc * 4 + pi;
                uint32_t addr = sb + (uint32_t)(((np * 2 + kt) * 32 + lane) * 16);
                LDS128(b[pi][0], b[pi][1], b[pi][2], b[pi][3], addr);
            }
#pragma unroll
            for (int mi = 0; mi < 4; mi++)
#pragma unroll
                for (int pi = 0; pi < 4; pi++) {
                    MMA_F16(acc[mi][pi * 2],     a[mi], b[pi][0], b[pi][1]);
                    MMA_F16(acc[mi][pi * 2 + 1], a[mi], b[pi][2], b[pi][3]);
                }
        }
    }

    // Epilogue: each acc pair (c0,c1) belongs to (row r, cols n..n+1),
    // (c2,c3) to (row r+8, same cols). Scatter as half2 into U16 layout:
    //   fp16 idx = ((l>>1)*32768 + b*1024 + d)*8 + (l&1)*4 + g,
    // with m = mb*128 + r  -> l = m>>5, b = m&31 ; n -> d = n>>2, g = n&3.
    {
        const int n  = nb * BN + wc * 64 + (lane & 3) * 2;  // +ni*8
        const int m0 = mb * BM + wr * 64 + (lane >> 2);     // +mi*16, +8
#pragma unroll
        for (int mi = 0; mi < 4; mi++) {
#pragma unroll
            for (int half = 0; half < 2; half++) {
                int m = m0 + mi * 16 + half * 8;
                int l = m >> 5;
                int b = m & 31;
                size_t base = ((size_t)(l >> 1) * 32768 + (size_t)b * 1024) * 8
                              + (size_t)(l & 1) * 4;
#pragma unroll
                for (int ni = 0; ni < 8; ni++) {
                    int nn = n + ni * 8;
                    int d  = nn >> 2;
                    int g  = nn & 3;
                    __half2 v = __floats2half2_rn(acc[mi][ni][half * 2],
                                                  acc[mi][ni][half * 2 + 1]);
                    *(__half2*)(U16 + base + (size_t)d * 8 + g) = v;
                }
            }
        }
    }
}

// ---------------------------------------------------------------------------
// SRU scan: one thread per (b,d) lane. U16 packs 2 timesteps per 16B:
// uint4 @ ((l>>1)*32768 + t) -> fp16[8] = {u0..u3 of l, u0..u3 of l+1}.
// 8-deep uint4 prefetch -> 16 timesteps per iteration.
// ---------------------------------------------------------------------------
__device__ __forceinline__ float sigmoidf_fast(float z) {
    return 1.0f / (1.0f + __expf(-z));
}

__global__ __launch_bounds__(256) void sru_scan_kernel(
    const __half* __restrict__ U16,
    const float* __restrict__ c0,
    const float* __restrict__ V,
    const float* __restrict__ bias,
    float* __restrict__ h_out,
    float* __restrict__ c_out)
{
    const int t = blockIdx.x * blockDim.x + threadIdx.x;   // 0..32767 = b*1024+d
    const int d = t & (D_DIM - 1);

    const float vf = V[d];
    const float vr = V[D_DIM + d];
    const float bf = bias[d];
    const float br = bias[D_DIM + d];
    float c = c0[t];

    const uint4* __restrict__ Up = (const uint4*)U16 + t;  // stride 32768 per l-pair
    float* __restrict__ hp = h_out + t;

    uint4 buf[8];
#pragma unroll
    for (int j = 0; j < 8; j++) buf[j] = Up[(size_t)j * (B_DIM * D_DIM)];

    for (int lp = 0; lp < L_DIM / 2; lp += 8) {
        uint4 cur[8];
#pragma unroll
        for (int j = 0; j < 8; j++) cur[j] = buf[j];
        if (lp + 8 < L_DIM / 2) {
#pragma unroll
            for (int j = 0; j < 8; j++)
                buf[j] = Up[(size_t)(lp + 8 + j) * (B_DIM * D_DIM)];
        }
#pragma unroll
        for (int j = 0; j < 8; j++) {
            const __half2* hh = (const __half2*)&cur[j];
#pragma unroll
            for (int s = 0; s < 2; s++) {
                float2 g01 = __half22float2(hh[s * 2]);
                float2 g23 = __half22float2(hh[s * 2 + 1]);
                float f = sigmoidf_fast(g01.y + c * vf + bf);
                float r = sigmoidf_fast(g23.x + c * vr + br);
                c = g01.x + (c - g01.x) * f;
                float h = (tanhf(c) - g23.y) * r + g23.y;
                hp[(size_t)((lp + j) * 2 + s) * (B_DIM * D_DIM)] = h;
            }
        }
    }

    if (c_out) c_out[t] = c;
}

// ---------------------------------------------------------------------------
// Launch
// ---------------------------------------------------------------------------
extern "C" void kernel_launch(void* const* d_in, const int* in_sizes, int n_in,
                              void* d_out, int out_size)
{
    const float* x    = (const float*)d_in[0];   // (L,B,IN)
    const float* c0   = (const float*)d_in[1];   // (B,D)
    const float* W    = (const float*)d_in[2];   // (IN,4D)
    const float* V    = (const float*)d_in[3];   // (2D)
    const float* bias = (const float*)d_in[4];   // (2D)
    float* out = (float*)d_out;

    __half *U16 = nullptr, *Ap = nullptr, *Bp = nullptr;
    cudaGetSymbolAddress((void**)&U16, g_U16);
    cudaGetSymbolAddress((void**)&Ap, g_Ap);
    cudaGetSymbolAddress((void**)&Bp, g_Bp);

    cudaFuncSetAttribute(gemm_f16_mma_kernel,
                         cudaFuncAttributeMaxDynamicSharedMemorySize, GEMM_SMEM);

    prep_x_kernel<<<16384, 256>>>(x, Ap);
    prep_W_kernel<<<2048, 256>>>(W, Bp);

    gemm_f16_mma_kernel<<<dim3(N_DIM / BN, M_DIM / BM), 256, GEMM_SMEM>>>(
        Ap, Bp, U16);

    const size_t LBD = (size_t)L_DIM * B_DIM * D_DIM;
    float* c_out = ((size_t)out_size > LBD) ? (out + LBD) : nullptr;
    sru_scan_kernel<<<(B_DIM * D_DIM) / 256, 256>>>(U16, c0, V, bias, out, c_out);
}

// round 9
// speedup vs baseline: 4.9881x; 1.1364x over previous
#include <cuda_runtime.h>
#include <cuda_fp16.h>
#include <cstdint>

// ---------------------------------------------------------------------------
// Problem constants
// ---------------------------------------------------------------------------
#define L_DIM 1024
#define B_DIM 32
#define IN_DIM 1024
#define D_DIM 1024
#define M_DIM (L_DIM * B_DIM)      // 32768
#define N_DIM (4 * D_DIM)          // 4096
#define K_DIM IN_DIM               // 1024

// GEMM tiling (fp16 operands)
#define BM 128
#define BN 256
#define BKB 64                     // K per stage
#define NSTG (K_DIM / BKB)         // 16 stages
#define ASTG_B (BM * BKB * 2)      // 16384 B / stage
#define BSTG_B (BN * BKB * 2)      // 32768 B / stage
#define STG_B (ASTG_B + BSTG_B)    // 49152 B
#define NPIPE 3
#define GEMM_SMEM (NPIPE * STG_B)  // 147456 B

// Scratch (device globals; no allocation allowed)
// U stored fp16, layout [l/2][s=b*1024+d][8] : fp16 idx = ((l>>1)*32768+s)*8 + (l&1)*4 + g
__device__ __half g_U16[(size_t)M_DIM * N_DIM];         // 256 MB
__device__ __half g_Ap[(size_t)M_DIM * K_DIM];          // 64 MB  fragment-ordered x
__device__ __half g_Bp[(size_t)N_DIM * K_DIM];          // 8 MB   fragment-ordered W

// ---------------------------------------------------------------------------
// helpers
// ---------------------------------------------------------------------------
__device__ __forceinline__ uint32_t smem_u32(const void* p) {
    uint32_t a;
    asm("{ .reg .u64 t; cvta.to.shared.u64 t, %1; cvt.u32.u64 %0, t; }"
        : "=r"(a) : "l"(p));
    return a;
}
__device__ __forceinline__ void cp16(uint32_t s, const void* g) {
    asm volatile("cp.async.cg.shared.global [%0], [%1], 16;" :: "r"(s), "l"(g));
}
__device__ __forceinline__ uint32_t h2_u32(__half2 h) {
    uint32_t u;
    memcpy(&u, &h, 4);
    return u;
}

#define LDS128(r0, r1, r2, r3, addr)                                           \
    asm volatile("ld.shared.v4.b32 {%0,%1,%2,%3}, [%4];"                       \
                 : "=r"(r0), "=r"(r1), "=r"(r2), "=r"(r3) : "r"(addr))

#define MMA_F16(d, a, b0, b1)                                                  \
    asm volatile(                                                              \
        "mma.sync.aligned.m16n8k16.row.col.f32.f16.f16.f32 "                   \
        "{%0,%1,%2,%3}, {%4,%5,%6,%7}, {%8,%9}, {%0,%1,%2,%3};"                \
        : "+f"((d)[0]), "+f"((d)[1]), "+f"((d)[2]), "+f"((d)[3])               \
        : "r"((a)[0]), "r"((a)[1]), "r"((a)[2]), "r"((a)[3]),                  \
          "r"(b0), "r"(b1))

// ---------------------------------------------------------------------------
// Prep A: x (fp32) -> g_Ap, fp16, m16n8k16 A-fragment order.
// (Layout defined on 32-wide k blocks; BKB=64 stages consume 2 consecutive.)
// ---------------------------------------------------------------------------
__global__ __launch_bounds__(256) void prep_x_kernel(
    const float* __restrict__ x, __half* __restrict__ Ap)
{
    int T = blockIdx.x * 8 + (threadIdx.x >> 5);
    int t = threadIdx.x & 31;
    int kt    = T & 1;
    int mt    = (T >> 1) & 7;
    int k_blk = (T >> 4) & 31;
    int m_blk = T >> 9;
    int r = m_blk * BM + mt * 16 + (t >> 2);
    int c = k_blk * 32 + kt * 16 + (t & 3) * 2;
    const float* xr = x + (size_t)r * K_DIM + c;
    float2 v0 = *(const float2*)xr;
    float2 v1 = *(const float2*)(xr + (size_t)8 * K_DIM);
    float2 v2 = *(const float2*)(xr + 8);
    float2 v3 = *(const float2*)(xr + (size_t)8 * K_DIM + 8);
    uint4 o;
    o.x = h2_u32(__floats2half2_rn(v0.x, v0.y));
    o.y = h2_u32(__floats2half2_rn(v1.x, v1.y));
    o.z = h2_u32(__floats2half2_rn(v2.x, v2.y));
    o.w = h2_u32(__floats2half2_rn(v3.x, v3.y));
    ((uint4*)Ap)[(size_t)T * 32 + t] = o;
}

// ---------------------------------------------------------------------------
// Prep B: W [K][N] fp32 -> g_Bp, fp16, m16n8k16 B-fragment order (col-major).
// ---------------------------------------------------------------------------
__global__ __launch_bounds__(256) void prep_W_kernel(
    const float* __restrict__ W, __half* __restrict__ Bp)
{
    int T = blockIdx.x * 8 + (threadIdx.x >> 5);
    int t = threadIdx.x & 31;
    int kt    = T & 1;
    int np    = (T >> 1) & 15;
    int k_blk = (T >> 5) & 31;
    int n_blk = T >> 10;
    int k = k_blk * 32 + kt * 16 + (t & 3) * 2;
    int n = n_blk * BN + np * 16 + (t >> 2);
    const float* wp = W + (size_t)k * N_DIM + n;
    float w0  = wp[0];
    float w1  = wp[N_DIM];
    float w8  = wp[(size_t)8 * N_DIM];
    float w9  = wp[(size_t)9 * N_DIM];
    float w0b = wp[8];
    float w1b = wp[N_DIM + 8];
    float w8b = wp[(size_t)8 * N_DIM + 8];
    float w9b = wp[(size_t)9 * N_DIM + 8];
    uint4 o;
    o.x = h2_u32(__floats2half2_rn(w0, w1));
    o.y = h2_u32(__floats2half2_rn(w8, w9));
    o.z = h2_u32(__floats2half2_rn(w0b, w1b));
    o.w = h2_u32(__floats2half2_rn(w8b, w9b));
    ((uint4*)Bp)[(size_t)T * 32 + t] = o;
}

// ---------------------------------------------------------------------------
// GEMM: U16 = Ap . Bp^T via mma.sync m16n8k16 fp16 (fp32 accum).
// CTA 128x256, 8 warps (2x4), warp tile 64x64, BK=64, 3-stage cp.async.
// Epilogue converts to fp16 and scatters into the scan-friendly U16 layout.
// ---------------------------------------------------------------------------
__global__ __launch_bounds__(256, 1) void gemm_f16_mma_kernel(
    const __half* __restrict__ Ap,
    const __half* __restrict__ Bp,
    __half* __restrict__ U16)
{
    extern __shared__ __align__(16) char smem[];
    const uint32_t sbase = smem_u32(smem);
    const int tid  = threadIdx.x;
    const int wid  = tid >> 5;
    const int lane = tid & 31;
    const int wr   = wid >> 2;     // 0..1: 64-row slab
    const int wc   = wid & 3;      // 0..3: 64-col slab
    const int mb   = blockIdx.y;
    const int nb   = blockIdx.x;

    const char* gA = (const char*)(Ap) + (size_t)mb * NSTG * ASTG_B;
    const char* gB = (const char*)(Bp) + (size_t)nb * NSTG * BSTG_B;

    // buffer index cycles 0,1,2 (NSTG % NPIPE != 0, use mod)
    auto load_stage = [&](int s) {
        uint32_t sa = sbase + (uint32_t)(s % NPIPE) * STG_B;
        const char* ga = gA + (size_t)s * ASTG_B;
        const char* gb = gB + (size_t)s * BSTG_B;
#pragma unroll
        for (int i = 0; i < 4; i++)
            cp16(sa + tid * 16 + i * 4096, ga + tid * 16 + i * 4096);
        uint32_t sb = sa + ASTG_B;
#pragma unroll
        for (int i = 0; i < 8; i++)
            cp16(sb + tid * 16 + i * 4096, gb + tid * 16 + i * 4096);
        asm volatile("cp.async.commit_group;" ::: "memory");
    };

    load_stage(0);
    load_stage(1);

    float acc[4][8][4] = {};

    for (int kb = 0; kb < NSTG; kb++) {
        if (kb < NSTG - 1) asm volatile("cp.async.wait_group 1;" ::: "memory");
        else               asm volatile("cp.async.wait_group 0;" ::: "memory");
        __syncthreads();

        if (kb + 2 < NSTG) load_stage(kb + 2);

        uint32_t sstage = sbase + (uint32_t)(kb % NPIPE) * STG_B;

#pragma unroll
        for (int ks = 0; ks < 2; ks++) {
            uint32_t sa = sstage + (uint32_t)ks * 8192;
            uint32_t sb = sstage + ASTG_B + (uint32_t)ks * 16384;
#pragma unroll
            for (int kt = 0; kt < 2; kt++) {
                uint32_t a[4][4];
#pragma unroll
                for (int mi = 0; mi < 4; mi++) {
                    int mt = wr * 4 + mi;
                    uint32_t addr = sa + (uint32_t)(((mt * 2 + kt) * 32 + lane) * 16);
                    LDS128(a[mi][0], a[mi][1], a[mi][2], a[mi][3], addr);
                }
                uint32_t b[4][4];
#pragma unroll
                for (int pi = 0; pi < 4; pi++) {
                    int np = wc * 4 + pi;
                    uint32_t addr = sb + (uint32_t)(((np * 2 + kt) * 32 + lane) * 16);
                    LDS128(b[pi][0], b[pi][1], b[pi][2], b[pi][3], addr);
                }
#pragma unroll
                for (int mi = 0; mi < 4; mi++)
#pragma unroll
                    for (int pi = 0; pi < 4; pi++) {
                        MMA_F16(acc[mi][pi * 2],     a[mi], b[pi][0], b[pi][1]);
                        MMA_F16(acc[mi][pi * 2 + 1], a[mi], b[pi][2], b[pi][3]);
                    }
            }
        }
    }

    // Epilogue: scatter fp16 pairs into U16 layout:
    //   fp16 idx = ((l>>1)*32768 + b*1024 + d)*8 + (l&1)*4 + g
    // with m = mb*128 + r -> l = m>>5, b = m&31 ; n -> d = n>>2, g = n&3.
    {
        const int n  = nb * BN + wc * 64 + (lane & 3) * 2;  // +ni*8
        const int m0 = mb * BM + wr * 64 + (lane >> 2);     // +mi*16, +8
#pragma unroll
        for (int mi = 0; mi < 4; mi++) {
#pragma unroll
            for (int half = 0; half < 2; half++) {
                int m = m0 + mi * 16 + half * 8;
                int l = m >> 5;
                int b = m & 31;
                size_t base = ((size_t)(l >> 1) * 32768 + (size_t)b * 1024) * 8
                              + (size_t)(l & 1) * 4;
#pragma unroll
                for (int ni = 0; ni < 8; ni++) {
                    int nn = n + ni * 8;
                    int d  = nn >> 2;
                    int g  = nn & 3;
                    __half2 v = __floats2half2_rn(acc[mi][ni][half * 2],
                                                  acc[mi][ni][half * 2 + 1]);
                    *(__half2*)(U16 + base + (size_t)d * 8 + g) = v;
                }
            }
        }
    }
}

// ---------------------------------------------------------------------------
// SRU scan: one thread per (b,d) lane; HW tanh.approx for all gates.
// U16 packs 2 timesteps per 16B; 8-deep uint4 prefetch.
// ---------------------------------------------------------------------------
__device__ __forceinline__ float tanh_fast(float x) {
    float r;
    asm("tanh.approx.f32 %0, %1;" : "=f"(r) : "f"(x));
    return r;
}
__device__ __forceinline__ float sigmoid_fast(float z) {
    return fmaf(tanh_fast(z * 0.5f), 0.5f, 0.5f);
}

__global__ __launch_bounds__(256) void sru_scan_kernel(
    const __half* __restrict__ U16,
    const float* __restrict__ c0,
    const float* __restrict__ V,
    const float* __restrict__ bias,
    float* __restrict__ h_out,
    float* __restrict__ c_out)
{
    const int t = blockIdx.x * blockDim.x + threadIdx.x;   // 0..32767 = b*1024+d
    const int d = t & (D_DIM - 1);

    const float vf = V[d];
    const float vr = V[D_DIM + d];
    const float bf = bias[d];
    const float br = bias[D_DIM + d];
    float c = c0[t];

    const uint4* __restrict__ Up = (const uint4*)U16 + t;  // stride 32768 per l-pair
    float* __restrict__ hp = h_out + t;

    uint4 buf[8];
#pragma unroll
    for (int j = 0; j < 8; j++) buf[j] = Up[(size_t)j * (B_DIM * D_DIM)];

    for (int lp = 0; lp < L_DIM / 2; lp += 8) {
        uint4 cur[8];
#pragma unroll
        for (int j = 0; j < 8; j++) cur[j] = buf[j];
        if (lp + 8 < L_DIM / 2) {
#pragma unroll
            for (int j = 0; j < 8; j++)
                buf[j] = Up[(size_t)(lp + 8 + j) * (B_DIM * D_DIM)];
        }
#pragma unroll
        for (int j = 0; j < 8; j++) {
            const __half2* hh = (const __half2*)&cur[j];
#pragma unroll
            for (int s = 0; s < 2; s++) {
                float2 g01 = __half22float2(hh[s * 2]);
                float2 g23 = __half22float2(hh[s * 2 + 1]);
                float f = sigmoid_fast(g01.y + c * vf + bf);
                float r = sigmoid_fast(g23.x + c * vr + br);
                c = g01.x + (c - g01.x) * f;
                float h = (tanh_fast(c) - g23.y) * r + g23.y;
                hp[(size_t)((lp + j) * 2 + s) * (B_DIM * D_DIM)] = h;
            }
        }
    }

    if (c_out) c_out[t] = c;
}

// ---------------------------------------------------------------------------
// Launch
// ---------------------------------------------------------------------------
extern "C" void kernel_launch(void* const* d_in, const int* in_sizes, int n_in,
                              void* d_out, int out_size)
{
    const float* x    = (const float*)d_in[0];   // (L,B,IN)
    const float* c0   = (const float*)d_in[1];   // (B,D)
    const float* W    = (const float*)d_in[2];   // (IN,4D)
    const float* V    = (const float*)d_in[3];   // (2D)
    const float* bias = (const float*)d_in[4];   // (2D)
    float* out = (float*)d_out;

    __half *U16 = nullptr, *Ap = nullptr, *Bp = nullptr;
    cudaGetSymbolAddress((void**)&U16, g_U16);
    cudaGetSymbolAddress((void**)&Ap, g_Ap);
    cudaGetSymbolAddress((void**)&Bp, g_Bp);

    cudaFuncSetAttribute(gemm_f16_mma_kernel,
                         cudaFuncAttributeMaxDynamicSharedMemorySize, GEMM_SMEM);

    prep_x_kernel<<<16384, 256>>>(x, Ap);
    prep_W_kernel<<<2048, 256>>>(W, Bp);

    gemm_f16_mma_kernel<<<dim3(N_DIM / BN, M_DIM / BM), 256, GEMM_SMEM>>>(
        Ap, Bp, U16);

    const size_t LBD = (size_t)L_DIM * B_DIM * D_DIM;
    float* c_out = ((size_t)out_size > LBD) ? (out + LBD) : nullptr;
    sru_scan_kernel<<<(B_DIM * D_DIM) / 256, 256>>>(U16, c0, V, bias, out, c_out);
}

// round 10
// speedup vs baseline: 5.4073x; 1.0840x over previous
#include <cuda_runtime.h>
#include <cuda_fp16.h>
#include <cstdint>

// ---------------------------------------------------------------------------
// Problem constants
// ---------------------------------------------------------------------------
#define L_DIM 1024
#define B_DIM 32
#define IN_DIM 1024
#define D_DIM 1024
#define M_DIM (L_DIM * B_DIM)      // 32768
#define N_DIM (4 * D_DIM)          // 4096
#define K_DIM IN_DIM               // 1024

// GEMM tiling (fp16 operands), 2 CTAs/SM
#define BM 128
#define BN 128
#define BKB 64                     // K per stage
#define NSTG (K_DIM / BKB)         // 16 stages
#define ASTG_B (BM * BKB * 2)      // 16384 B / stage
#define BSTG_B (BN * BKB * 2)      // 16384 B / stage
#define STG_B (ASTG_B + BSTG_B)    // 32768 B
#define NPIPE 3
#define GEMM_SMEM (NPIPE * STG_B)  // 98304 B  -> 2 CTAs/SM

// Scratch (device globals; no allocation allowed)
// U stored fp16, layout [l/2][s=b*1024+d][8] : fp16 idx = ((l>>1)*32768+s)*8 + (l&1)*4 + g
__device__ __half g_U16[(size_t)M_DIM * N_DIM];         // 256 MB
__device__ __half g_Ap[(size_t)M_DIM * K_DIM];          // 64 MB  fragment-ordered x
__device__ __half g_Bp[(size_t)N_DIM * K_DIM];          // 8 MB   fragment-ordered W

// ---------------------------------------------------------------------------
// helpers
// ---------------------------------------------------------------------------
__device__ __forceinline__ uint32_t smem_u32(const void* p) {
    uint32_t a;
    asm("{ .reg .u64 t; cvta.to.shared.u64 t, %1; cvt.u32.u64 %0, t; }"
        : "=r"(a) : "l"(p));
    return a;
}
__device__ __forceinline__ void cp16(uint32_t s, const void* g) {
    asm volatile("cp.async.cg.shared.global [%0], [%1], 16;" :: "r"(s), "l"(g));
}
__device__ __forceinline__ uint32_t h2_u32(__half2 h) {
    uint32_t u;
    memcpy(&u, &h, 4);
    return u;
}

#define LDS128(r0, r1, r2, r3, addr)                                           \
    asm volatile("ld.shared.v4.b32 {%0,%1,%2,%3}, [%4];"                       \
                 : "=r"(r0), "=r"(r1), "=r"(r2), "=r"(r3) : "r"(addr))

#define MMA_F16(d, a, b0, b1)                                                  \
    asm volatile(                                                              \
        "mma.sync.aligned.m16n8k16.row.col.f32.f16.f16.f32 "                   \
        "{%0,%1,%2,%3}, {%4,%5,%6,%7}, {%8,%9}, {%0,%1,%2,%3};"                \
        : "+f"((d)[0]), "+f"((d)[1]), "+f"((d)[2]), "+f"((d)[3])               \
        : "r"((a)[0]), "r"((a)[1]), "r"((a)[2]), "r"((a)[3]),                  \
          "r"(b0), "r"(b1))

// ---------------------------------------------------------------------------
// Prep A: x (fp32) -> g_Ap, fp16, m16n8k16 A-fragment order.
// Layout per (m_blk128, k_blk32): 8 mt x 2 kt x 32 lanes x 16B = 8 KB tiles,
// k_blk fastest -> one BK=64 stage reads 16 KB contiguous.
// ---------------------------------------------------------------------------
__global__ __launch_bounds__(256) void prep_x_kernel(
    const float* __restrict__ x, __half* __restrict__ Ap)
{
    int T = blockIdx.x * 8 + (threadIdx.x >> 5);
    int t = threadIdx.x & 31;
    int kt    = T & 1;
    int mt    = (T >> 1) & 7;
    int k_blk = (T >> 4) & 31;
    int m_blk = T >> 9;
    int r = m_blk * BM + mt * 16 + (t >> 2);
    int c = k_blk * 32 + kt * 16 + (t & 3) * 2;
    const float* xr = x + (size_t)r * K_DIM + c;
    float2 v0 = *(const float2*)xr;
    float2 v1 = *(const float2*)(xr + (size_t)8 * K_DIM);
    float2 v2 = *(const float2*)(xr + 8);
    float2 v3 = *(const float2*)(xr + (size_t)8 * K_DIM + 8);
    uint4 o;
    o.x = h2_u32(__floats2half2_rn(v0.x, v0.y));
    o.y = h2_u32(__floats2half2_rn(v1.x, v1.y));
    o.z = h2_u32(__floats2half2_rn(v2.x, v2.y));
    o.w = h2_u32(__floats2half2_rn(v3.x, v3.y));
    ((uint4*)Ap)[(size_t)T * 32 + t] = o;
}

// ---------------------------------------------------------------------------
// Prep B: W [K][N] fp32 -> g_Bp, fp16, m16n8k16 B-fragment order (col-major).
// Layout per (n_blk128, k_blk32): 8 np x 2 kt x 32 lanes x 16B = 8 KB tiles.
// ---------------------------------------------------------------------------
__global__ __launch_bounds__(256) void prep_W_kernel(
    const float* __restrict__ W, __half* __restrict__ Bp)
{
    int T = blockIdx.x * 8 + (threadIdx.x >> 5);
    int t = threadIdx.x & 31;
    int kt    = T & 1;
    int np    = (T >> 1) & 7;
    int k_blk = (T >> 4) & 31;
    int n_blk = T >> 9;
    int k = k_blk * 32 + kt * 16 + (t & 3) * 2;
    int n = n_blk * BN + np * 16 + (t >> 2);
    const float* wp = W + (size_t)k * N_DIM + n;
    float w0  = wp[0];
    float w1  = wp[N_DIM];
    float w8  = wp[(size_t)8 * N_DIM];
    float w9  = wp[(size_t)9 * N_DIM];
    float w0b = wp[8];
    float w1b = wp[N_DIM + 8];
    float w8b = wp[(size_t)8 * N_DIM + 8];
    float w9b = wp[(size_t)9 * N_DIM + 8];
    uint4 o;
    o.x = h2_u32(__floats2half2_rn(w0, w1));
    o.y = h2_u32(__floats2half2_rn(w8, w9));
    o.z = h2_u32(__floats2half2_rn(w0b, w1b));
    o.w = h2_u32(__floats2half2_rn(w8b, w9b));
    ((uint4*)Bp)[(size_t)T * 32 + t] = o;
}

// ---------------------------------------------------------------------------
// GEMM: U16 = Ap . Bp^T via mma.sync m16n8k16 fp16 (fp32 accum).
// CTA 128x128, 8 warps (2x4), warp tile 64x32, BK=64, 3-stage cp.async,
// 2 CTAs/SM for sync/epilogue overlap.
// ---------------------------------------------------------------------------
__global__ __launch_bounds__(256, 2) void gemm_f16_mma_kernel(
    const __half* __restrict__ Ap,
    const __half* __restrict__ Bp,
    __half* __restrict__ U16)
{
    extern __shared__ __align__(16) char smem[];
    const uint32_t sbase = smem_u32(smem);
    const int tid  = threadIdx.x;
    const int wid  = tid >> 5;
    const int lane = tid & 31;
    const int wr   = wid >> 2;     // 0..1: 64-row slab
    const int wc   = wid & 3;      // 0..3: 32-col slab
    const int mb   = blockIdx.y;
    const int nb   = blockIdx.x;

    const char* gA = (const char*)(Ap) + (size_t)mb * NSTG * ASTG_B;
    const char* gB = (const char*)(Bp) + (size_t)nb * NSTG * BSTG_B;

    auto load_stage = [&](int s) {
        uint32_t sa = sbase + (uint32_t)(s % NPIPE) * STG_B;
        const char* ga = gA + (size_t)s * ASTG_B;
        const char* gb = gB + (size_t)s * BSTG_B;
#pragma unroll
        for (int i = 0; i < 4; i++)
            cp16(sa + tid * 16 + i * 4096, ga + tid * 16 + i * 4096);
        uint32_t sb = sa + ASTG_B;
#pragma unroll
        for (int i = 0; i < 4; i++)
            cp16(sb + tid * 16 + i * 4096, gb + tid * 16 + i * 4096);
        asm volatile("cp.async.commit_group;" ::: "memory");
    };

    load_stage(0);
    load_stage(1);

    float acc[4][4][4] = {};

    for (int kb = 0; kb < NSTG; kb++) {
        if (kb < NSTG - 1) asm volatile("cp.async.wait_group 1;" ::: "memory");
        else               asm volatile("cp.async.wait_group 0;" ::: "memory");
        __syncthreads();

        if (kb + 2 < NSTG) load_stage(kb + 2);

        uint32_t sstage = sbase + (uint32_t)(kb % NPIPE) * STG_B;

#pragma unroll
        for (int ks = 0; ks < 2; ks++) {
            uint32_t sa = sstage + (uint32_t)ks * 8192;
            uint32_t sb = sstage + ASTG_B + (uint32_t)ks * 8192;
#pragma unroll
            for (int kt = 0; kt < 2; kt++) {
                uint32_t a[4][4];
#pragma unroll
                for (int mi = 0; mi < 4; mi++) {
                    int mt = wr * 4 + mi;
                    uint32_t addr = sa + (uint32_t)(((mt * 2 + kt) * 32 + lane) * 16);
                    LDS128(a[mi][0], a[mi][1], a[mi][2], a[mi][3], addr);
                }
                uint32_t b[2][4];
#pragma unroll
                for (int pi = 0; pi < 2; pi++) {
                    int np = wc * 2 + pi;
                    uint32_t addr = sb + (uint32_t)(((np * 2 + kt) * 32 + lane) * 16);
                    LDS128(b[pi][0], b[pi][1], b[pi][2], b[pi][3], addr);
                }
#pragma unroll
                for (int mi = 0; mi < 4; mi++)
#pragma unroll
                    for (int pi = 0; pi < 2; pi++) {
                        MMA_F16(acc[mi][pi * 2],     a[mi], b[pi][0], b[pi][1]);
                        MMA_F16(acc[mi][pi * 2 + 1], a[mi], b[pi][2], b[pi][3]);
                    }
            }
        }
    }

    // Epilogue: scatter fp16 pairs into U16 layout:
    //   fp16 idx = ((l>>1)*32768 + b*1024 + d)*8 + (l&1)*4 + g
    // with m = mb*128 + r -> l = m>>5, b = m&31 ; n -> d = n>>2, g = n&3.
    {
        const int n  = nb * BN + wc * 32 + (lane & 3) * 2;  // +ni*8
        const int m0 = mb * BM + wr * 64 + (lane >> 2);     // +mi*16, +8
#pragma unroll
        for (int mi = 0; mi < 4; mi++) {
#pragma unroll
            for (int half = 0; half < 2; half++) {
                int m = m0 + mi * 16 + half * 8;
                int l = m >> 5;
                int b = m & 31;
                size_t base = ((size_t)(l >> 1) * 32768 + (size_t)b * 1024) * 8
                              + (size_t)(l & 1) * 4;
#pragma unroll
                for (int ni = 0; ni < 4; ni++) {
                    int nn = n + ni * 8;
                    int d  = nn >> 2;
                    int g  = nn & 3;
                    __half2 v = __floats2half2_rn(acc[mi][ni][half * 2],
                                                  acc[mi][ni][half * 2 + 1]);
                    *(__half2*)(U16 + base + (size_t)d * 8 + g) = v;
                }
            }
        }
    }
}

// ---------------------------------------------------------------------------
// SRU scan: one thread per (b,d) lane; HW tanh.approx for all gates.
// U16 packs 2 timesteps per 16B; 8-deep uint4 prefetch.
// ---------------------------------------------------------------------------
__device__ __forceinline__ float tanh_fast(float x) {
    float r;
    asm("tanh.approx.f32 %0, %1;" : "=f"(r) : "f"(x));
    return r;
}
__device__ __forceinline__ float sigmoid_fast(float z) {
    return fmaf(tanh_fast(z * 0.5f), 0.5f, 0.5f);
}

__global__ __launch_bounds__(256) void sru_scan_kernel(
    const __half* __restrict__ U16,
    const float* __restrict__ c0,
    const float* __restrict__ V,
    const float* __restrict__ bias,
    float* __restrict__ h_out,
    float* __restrict__ c_out)
{
    const int t = blockIdx.x * blockDim.x + threadIdx.x;   // 0..32767 = b*1024+d
    const int d = t & (D_DIM - 1);

    const float vf = V[d];
    const float vr = V[D_DIM + d];
    const float bf = bias[d];
    const float br = bias[D_DIM + d];
    float c = c0[t];

    const uint4* __restrict__ Up = (const uint4*)U16 + t;  // stride 32768 per l-pair
    float* __restrict__ hp = h_out + t;

    uint4 buf[8];
#pragma unroll
    for (int j = 0; j < 8; j++) buf[j] = Up[(size_t)j * (B_DIM * D_DIM)];

    for (int lp = 0; lp < L_DIM / 2; lp += 8) {
        uint4 cur[8];
#pragma unroll
        for (int j = 0; j < 8; j++) cur[j] = buf[j];
        if (lp + 8 < L_DIM / 2) {
#pragma unroll
            for (int j = 0; j < 8; j++)
                buf[j] = Up[(size_t)(lp + 8 + j) * (B_DIM * D_DIM)];
        }
#pragma unroll
        for (int j = 0; j < 8; j++) {
            const __half2* hh = (const __half2*)&cur[j];
#pragma unroll
            for (int s = 0; s < 2; s++) {
                float2 g01 = __half22float2(hh[s * 2]);
                float2 g23 = __half22float2(hh[s * 2 + 1]);
                float f = sigmoid_fast(g01.y + c * vf + bf);
                float r = sigmoid_fast(g23.x + c * vr + br);
                c = g01.x + (c - g01.x) * f;
                float h = (tanh_fast(c) - g23.y) * r + g23.y;
                hp[(size_t)((lp + j) * 2 + s) * (B_DIM * D_DIM)] = h;
            }
        }
    }

    if (c_out) c_out[t] = c;
}

// ---------------------------------------------------------------------------
// Launch
// ---------------------------------------------------------------------------
extern "C" void kernel_launch(void* const* d_in, const int* in_sizes, int n_in,
                              void* d_out, int out_size)
{
    const float* x    = (const float*)d_in[0];   // (L,B,IN)
    const float* c0   = (const float*)d_in[1];   // (B,D)
    const float* W    = (const float*)d_in[2];   // (IN,4D)
    const float* V    = (const float*)d_in[3];   // (2D)
    const float* bias = (const float*)d_in[4];   // (2D)
    float* out = (float*)d_out;

    __half *U16 = nullptr, *Ap = nullptr, *Bp = nullptr;
    cudaGetSymbolAddress((void**)&U16, g_U16);
    cudaGetSymbolAddress((void**)&Ap, g_Ap);
    cudaGetSymbolAddress((void**)&Bp, g_Bp);

    cudaFuncSetAttribute(gemm_f16_mma_kernel,
                         cudaFuncAttributeMaxDynamicSharedMemorySize, GEMM_SMEM);

    prep_x_kernel<<<16384, 256>>>(x, Ap);
    prep_W_kernel<<<2048, 256>>>(W, Bp);

    gemm_f16_mma_kernel<<<dim3(N_DIM / BN, M_DIM / BM), 256, GEMM_SMEM>>>(
        Ap, Bp, U16);

    const size_t LBD = (size_t)L_DIM * B_DIM * D_DIM;
    float* c_out = ((size_t)out_size > LBD) ? (out + LBD) : nullptr;
    sru_scan_kernel<<<(B_DIM * D_DIM) / 256, 256>>>(U16, c0, V, bias, out, c_out);
}

// round 11
// speedup vs baseline: 5.5582x; 1.0279x over previous
#include <cuda_runtime.h>
#include <cuda_fp16.h>
#include <cstdint>

// ---------------------------------------------------------------------------
// Problem constants
// ---------------------------------------------------------------------------
#define L_DIM 1024
#define B_DIM 32
#define IN_DIM 1024
#define D_DIM 1024
#define M_DIM (L_DIM * B_DIM)      // 32768
#define N_DIM (4 * D_DIM)          // 4096
#define K_DIM IN_DIM               // 1024

// GEMM tiling (fp16 operands), 2 CTAs/SM
#define BM 128
#define BN 128
#define BKB 64                     // K per stage
#define NSTG (K_DIM / BKB)         // 16 stages
#define ASTG_B (BM * BKB * 2)      // 16384 B / stage
#define BSTG_B (BN * BKB * 2)      // 16384 B / stage
#define STG_B (ASTG_B + BSTG_B)    // 32768 B
#define NPIPE 3
#define GEMM_SMEM (NPIPE * STG_B)  // 98304 B  -> 2 CTAs/SM

// Scratch (device globals; no allocation allowed)
// U stored fp16, layout [l/2][s=b*1024+d][8] : fp16 idx = ((l>>1)*32768+s)*8 + (l&1)*4 + g
__device__ __half g_U16[(size_t)M_DIM * N_DIM];         // 256 MB
__device__ __half g_Ap[(size_t)M_DIM * K_DIM];          // 64 MB  fragment-ordered x
__device__ __half g_Bp[(size_t)N_DIM * K_DIM];          // 8 MB   fragment-ordered W

// ---------------------------------------------------------------------------
// helpers
// ---------------------------------------------------------------------------
__device__ __forceinline__ uint32_t smem_u32(const void* p) {
    uint32_t a;
    asm("{ .reg .u64 t; cvta.to.shared.u64 t, %1; cvt.u32.u64 %0, t; }"
        : "=r"(a) : "l"(p));
    return a;
}
__device__ __forceinline__ void cp16(uint32_t s, const void* g) {
    asm volatile("cp.async.cg.shared.global [%0], [%1], 16;" :: "r"(s), "l"(g));
}
__device__ __forceinline__ uint32_t h2_u32(__half2 h) {
    uint32_t u;
    memcpy(&u, &h, 4);
    return u;
}

#define LDS128(r0, r1, r2, r3, addr)                                           \
    asm volatile("ld.shared.v4.b32 {%0,%1,%2,%3}, [%4];"                       \
                 : "=r"(r0), "=r"(r1), "=r"(r2), "=r"(r3) : "r"(addr))

#define MMA_F16(d, a, b0, b1)                                                  \
    asm volatile(                                                              \
        "mma.sync.aligned.m16n8k16.row.col.f32.f16.f16.f32 "                   \
        "{%0,%1,%2,%3}, {%4,%5,%6,%7}, {%8,%9}, {%0,%1,%2,%3};"                \
        : "+f"((d)[0]), "+f"((d)[1]), "+f"((d)[2]), "+f"((d)[3])               \
        : "r"((a)[0]), "r"((a)[1]), "r"((a)[2]), "r"((a)[3]),                  \
          "r"(b0), "r"(b1))

// ---------------------------------------------------------------------------
// Prep A: x (fp32) -> g_Ap, fp16, m16n8k16 A-fragment order.
// ---------------------------------------------------------------------------
__global__ __launch_bounds__(256) void prep_x_kernel(
    const float* __restrict__ x, __half* __restrict__ Ap)
{
    int T = blockIdx.x * 8 + (threadIdx.x >> 5);
    int t = threadIdx.x & 31;
    int kt    = T & 1;
    int mt    = (T >> 1) & 7;
    int k_blk = (T >> 4) & 31;
    int m_blk = T >> 9;
    int r = m_blk * BM + mt * 16 + (t >> 2);
    int c = k_blk * 32 + kt * 16 + (t & 3) * 2;
    const float* xr = x + (size_t)r * K_DIM + c;
    float2 v0 = *(const float2*)xr;
    float2 v1 = *(const float2*)(xr + (size_t)8 * K_DIM);
    float2 v2 = *(const float2*)(xr + 8);
    float2 v3 = *(const float2*)(xr + (size_t)8 * K_DIM + 8);
    uint4 o;
    o.x = h2_u32(__floats2half2_rn(v0.x, v0.y));
    o.y = h2_u32(__floats2half2_rn(v1.x, v1.y));
    o.z = h2_u32(__floats2half2_rn(v2.x, v2.y));
    o.w = h2_u32(__floats2half2_rn(v3.x, v3.y));
    ((uint4*)Ap)[(size_t)T * 32 + t] = o;
}

// ---------------------------------------------------------------------------
// Prep B: W [K][N] fp32 -> g_Bp, fp16, m16n8k16 B-fragment order (col-major).
// ---------------------------------------------------------------------------
__global__ __launch_bounds__(256) void prep_W_kernel(
    const float* __restrict__ W, __half* __restrict__ Bp)
{
    int T = blockIdx.x * 8 + (threadIdx.x >> 5);
    int t = threadIdx.x & 31;
    int kt    = T & 1;
    int np    = (T >> 1) & 7;
    int k_blk = (T >> 4) & 31;
    int n_blk = T >> 9;
    int k = k_blk * 32 + kt * 16 + (t & 3) * 2;
    int n = n_blk * BN + np * 16 + (t >> 2);
    const float* wp = W + (size_t)k * N_DIM + n;
    float w0  = wp[0];
    float w1  = wp[N_DIM];
    float w8  = wp[(size_t)8 * N_DIM];
    float w9  = wp[(size_t)9 * N_DIM];
    float w0b = wp[8];
    float w1b = wp[N_DIM + 8];
    float w8b = wp[(size_t)8 * N_DIM + 8];
    float w9b = wp[(size_t)9 * N_DIM + 8];
    uint4 o;
    o.x = h2_u32(__floats2half2_rn(w0, w1));
    o.y = h2_u32(__floats2half2_rn(w8, w9));
    o.z = h2_u32(__floats2half2_rn(w0b, w1b));
    o.w = h2_u32(__floats2half2_rn(w8b, w9b));
    ((uint4*)Bp)[(size_t)T * 32 + t] = o;
}

// ---------------------------------------------------------------------------
// GEMM: U16 = Ap . Bp^T via mma.sync m16n8k16 fp16 (fp32 accum).
// CTA 128x128, 8 warps (2x4), warp tile 64x32, BK=64, 3-stage cp.async,
// 2 CTAs/SM; fragment loads double-buffered across the 4 k-substeps.
// ---------------------------------------------------------------------------
__global__ __launch_bounds__(256, 2) void gemm_f16_mma_kernel(
    const __half* __restrict__ Ap,
    const __half* __restrict__ Bp,
    __half* __restrict__ U16)
{
    extern __shared__ __align__(16) char smem[];
    const uint32_t sbase = smem_u32(smem);
    const int tid  = threadIdx.x;
    const int wid  = tid >> 5;
    const int lane = tid & 31;
    const int wr   = wid >> 2;     // 0..1: 64-row slab
    const int wc   = wid & 3;      // 0..3: 32-col slab
    const int mb   = blockIdx.y;
    const int nb   = blockIdx.x;

    const char* gA = (const char*)(Ap) + (size_t)mb * NSTG * ASTG_B;
    const char* gB = (const char*)(Bp) + (size_t)nb * NSTG * BSTG_B;

    auto load_stage = [&](int s) {
        uint32_t sa = sbase + (uint32_t)(s % NPIPE) * STG_B;
        const char* ga = gA + (size_t)s * ASTG_B;
        const char* gb = gB + (size_t)s * BSTG_B;
#pragma unroll
        for (int i = 0; i < 4; i++)
            cp16(sa + tid * 16 + i * 4096, ga + tid * 16 + i * 4096);
        uint32_t sb = sa + ASTG_B;
#pragma unroll
        for (int i = 0; i < 4; i++)
            cp16(sb + tid * 16 + i * 4096, gb + tid * 16 + i * 4096);
        asm volatile("cp.async.commit_group;" ::: "memory");
    };

    load_stage(0);
    load_stage(1);

    float acc[4][4][4] = {};
    uint32_t afr[2][4][4];
    uint32_t bfr[2][2][4];

    const uint32_t aoff = (uint32_t)((wr * 4) * 2 * 32 + lane) * 16;  // + mi*1024 + kt*512
    const uint32_t boff = (uint32_t)((wc * 2) * 2 * 32 + lane) * 16;  // + pi*1024 + kt*512

    for (int kb = 0; kb < NSTG; kb++) {
        if (kb < NSTG - 1) asm volatile("cp.async.wait_group 1;" ::: "memory");
        else               asm volatile("cp.async.wait_group 0;" ::: "memory");
        __syncthreads();

        if (kb + 2 < NSTG) load_stage(kb + 2);

        uint32_t sstage = sbase + (uint32_t)(kb % NPIPE) * STG_B;

        // load fragments for substep kk: ks = kk>>1 selects 8KB half, kt = kk&1
        auto load_frags = [&](int kk, int buf) {
            uint32_t sa = sstage + (uint32_t)(kk >> 1) * 8192 + aoff
                        + (uint32_t)(kk & 1) * 512;
            uint32_t sb = sstage + ASTG_B + (uint32_t)(kk >> 1) * 8192 + boff
                        + (uint32_t)(kk & 1) * 512;
#pragma unroll
            for (int mi = 0; mi < 4; mi++)
                LDS128(afr[buf][mi][0], afr[buf][mi][1],
                       afr[buf][mi][2], afr[buf][mi][3], sa + mi * 1024);
#pragma unroll
            for (int pi = 0; pi < 2; pi++)
                LDS128(bfr[buf][pi][0], bfr[buf][pi][1],
                       bfr[buf][pi][2], bfr[buf][pi][3], sb + pi * 1024);
        };

        load_frags(0, 0);
#pragma unroll
        for (int kk = 0; kk < 4; kk++) {
            int cur = kk & 1;
            if (kk < 3) load_frags(kk + 1, cur ^ 1);
#pragma unroll
            for (int mi = 0; mi < 4; mi++)
#pragma unroll
                for (int pi = 0; pi < 2; pi++) {
                    MMA_F16(acc[mi][pi * 2],     afr[cur][mi],
                            bfr[cur][pi][0], bfr[cur][pi][1]);
                    MMA_F16(acc[mi][pi * 2 + 1], afr[cur][mi],
                            bfr[cur][pi][2], bfr[cur][pi][3]);
                }
        }
    }

    // Epilogue: scatter fp16 pairs into U16 layout:
    //   fp16 idx = ((l>>1)*32768 + b*1024 + d)*8 + (l&1)*4 + g
    // with m = mb*128 + r -> l = m>>5, b = m&31 ; n -> d = n>>2, g = n&3.
    {
        const int n  = nb * BN + wc * 32 + (lane & 3) * 2;  // +ni*8
        const int m0 = mb * BM + wr * 64 + (lane >> 2);     // +mi*16, +8
#pragma unroll
        for (int mi = 0; mi < 4; mi++) {
#pragma unroll
            for (int half = 0; half < 2; half++) {
                int m = m0 + mi * 16 + half * 8;
                int l = m >> 5;
                int b = m & 31;
                size_t base = ((size_t)(l >> 1) * 32768 + (size_t)b * 1024) * 8
                              + (size_t)(l & 1) * 4;
#pragma unroll
                for (int ni = 0; ni < 4; ni++) {
                    int nn = n + ni * 8;
                    int d  = nn >> 2;
                    int g  = nn & 3;
                    __half2 v = __floats2half2_rn(acc[mi][ni][half * 2],
                                                  acc[mi][ni][half * 2 + 1]);
                    *(__half2*)(U16 + base + (size_t)d * 8 + g) = v;
                }
            }
        }
    }
}

// ---------------------------------------------------------------------------
// SRU scan: one thread per (b,d) lane; HW tanh.approx for all gates.
// U16 packs 2 timesteps per 16B; 16-deep uint4 prefetch (256B in flight).
// ---------------------------------------------------------------------------
__device__ __forceinline__ float tanh_fast(float x) {
    float r;
    asm("tanh.approx.f32 %0, %1;" : "=f"(r) : "f"(x));
    return r;
}
__device__ __forceinline__ float sigmoid_fast(float z) {
    return fmaf(tanh_fast(z * 0.5f), 0.5f, 0.5f);
}

__global__ __launch_bounds__(128) void sru_scan_kernel(
    const __half* __restrict__ U16,
    const float* __restrict__ c0,
    const float* __restrict__ V,
    const float* __restrict__ bias,
    float* __restrict__ h_out,
    float* __restrict__ c_out)
{
    const int t = blockIdx.x * blockDim.x + threadIdx.x;   // 0..32767 = b*1024+d
    const int d = t & (D_DIM - 1);

    const float vf = V[d];
    const float vr = V[D_DIM + d];
    const float bf = bias[d];
    const float br = bias[D_DIM + d];
    float c = c0[t];

    const uint4* __restrict__ Up = (const uint4*)U16 + t;  // stride 32768 per l-pair
    float* __restrict__ hp = h_out + t;

    uint4 buf[16];
#pragma unroll
    for (int j = 0; j < 16; j++) buf[j] = Up[(size_t)j * (B_DIM * D_DIM)];

    for (int lp = 0; lp < L_DIM / 2; lp += 16) {
        uint4 cur[16];
#pragma unroll
        for (int j = 0; j < 16; j++) cur[j] = buf[j];
        if (lp + 16 < L_DIM / 2) {
#pragma unroll
            for (int j = 0; j < 16; j++)
                buf[j] = Up[(size_t)(lp + 16 + j) * (B_DIM * D_DIM)];
        }
#pragma unroll
        for (int j = 0; j < 16; j++) {
            const __half2* hh = (const __half2*)&cur[j];
#pragma unroll
            for (int s = 0; s < 2; s++) {
                float2 g01 = __half22float2(hh[s * 2]);
                float2 g23 = __half22float2(hh[s * 2 + 1]);
                float f = sigmoid_fast(g01.y + c * vf + bf);
                float r = sigmoid_fast(g23.x + c * vr + br);
                c = g01.x + (c - g01.x) * f;
                float h = (tanh_fast(c) - g23.y) * r + g23.y;
                hp[(size_t)((lp + j) * 2 + s) * (B_DIM * D_DIM)] = h;
            }
        }
    }

    if (c_out) c_out[t] = c;
}

// ---------------------------------------------------------------------------
// Launch
// ---------------------------------------------------------------------------
extern "C" void kernel_launch(void* const* d_in, const int* in_sizes, int n_in,
                              void* d_out, int out_size)
{
    const float* x    = (const float*)d_in[0];   // (L,B,IN)
    const float* c0   = (const float*)d_in[1];   // (B,D)
    const float* W    = (const float*)d_in[2];   // (IN,4D)
    const float* V    = (const float*)d_in[3];   // (2D)
    const float* bias = (const float*)d_in[4];   // (2D)
    float* out = (float*)d_out;

    __half *U16 = nullptr, *Ap = nullptr, *Bp = nullptr;
    cudaGetSymbolAddress((void**)&U16, g_U16);
    cudaGetSymbolAddress((void**)&Ap, g_Ap);
    cudaGetSymbolAddress((void**)&Bp, g_Bp);

    cudaFuncSetAttribute(gemm_f16_mma_kernel,
                         cudaFuncAttributeMaxDynamicSharedMemorySize, GEMM_SMEM);

    prep_x_kernel<<<16384, 256>>>(x, Ap);
    prep_W_kernel<<<2048, 256>>>(W, Bp);

    gemm_f16_mma_kernel<<<dim3(N_DIM / BN, M_DIM / BM), 256, GEMM_SMEM>>>(
        Ap, Bp, U16);

    const size_t LBD = (size_t)L_DIM * B_DIM * D_DIM;
    float* c_out = ((size_t)out_size > LBD) ? (out + LBD) : nullptr;
    sru_scan_kernel<<<(B_DIM * D_DIM) / 128, 128>>>(U16, c0, V, bias, out, c_out);
}